// round 6
// baseline (speedup 1.0000x reference)
#include <cuda_runtime.h>
#include <cstdint>

#define BB 2
#define NN 8192
#define CC 80
#define KCAP 128
#define CELLS 256          /* 16x16 spatial cells */
#define NT (NN/64)         /* 128 tiles per batch */

typedef unsigned long long u64;
typedef unsigned int u32;
typedef unsigned short u16;
typedef unsigned char u8;

/* output layout (concatenated flat float32, tuple order) */
#define OFF_BOXES 0
#define OFF_MS    (BB*NN*4)
#define OFF_LB    (OFF_MS + BB*NN)
#define OFF_KEEP  (OFF_LB + BB*NN)
#define OFF_ALL   (OFF_KEEP + BB*NN)

/* static device scratch */
__device__ u64    g_keys[BB][NN];
__device__ u8     g_validb[BB][NN];
__device__ u8     g_cell[BB][NN];
__device__ int    g_bins[BB][CELLS];
__device__ int    g_off[BB][CELLS];
__device__ u16    g_perm[BB][NN];        /* sorted pos -> original idx */
__device__ float4 g_sbox[BB][NN];        /* sorted box data */
__device__ float  g_sarea[BB][NN];
__device__ u64    g_skey[BB][NN];
__device__ u8     g_sval[BB][NN];
__device__ float4 g_taabb[BB][NT];       /* per-tile AABB */
__device__ int    g_cnt[BB][NN];         /* suppressor counts (sorted space) */
__device__ u16    g_list[BB][NN][KCAP];  /* suppressor lists  (sorted space) */

/* ------------------------------------------------------------------ */
__global__ void init_kernel()
{
    int idx = blockIdx.x * blockDim.x + threadIdx.x;
    if (idx < BB * NN) ((int*)g_cnt)[idx] = 0;
    if (idx < BB * CELLS) ((int*)g_bins)[idx] = 0;
}

/* ------------------------------------------------------------------ */
/* Kernel 1: sigmoid / max / argmax / decode / valid / keys / cell    */
__global__ void prep_kernel(const float* __restrict__ logits,
                            const float* __restrict__ deltas,
                            const float* __restrict__ anchors,
                            float* __restrict__ out)
{
    int wid  = (blockIdx.x * blockDim.x + threadIdx.x) >> 5;
    int lane = threadIdx.x & 31;
    if (wid >= BB * NN) return;
    int b = wid / NN, n = wid % NN;

    const float* lg = logits + (size_t)wid * CC;
    float* as_out   = out + OFF_ALL + (size_t)wid * CC;

    float v0 = lg[lane];
    float v1 = lg[lane + 32];
    float v2 = (lane < 16) ? lg[lane + 64] : -INFINITY;

    as_out[lane]      = 1.0f / (1.0f + expf(-v0));
    as_out[lane + 32] = 1.0f / (1.0f + expf(-v1));
    if (lane < 16) as_out[lane + 64] = 1.0f / (1.0f + expf(-v2));

    float mv = v0; int mi = lane;
    if (v1 > mv) { mv = v1; mi = lane + 32; }
    if (v2 > mv) { mv = v2; mi = lane + 64; }

    for (int off = 16; off; off >>= 1) {
        float ov = __shfl_down_sync(0xffffffffu, mv, off);
        int   oi = __shfl_down_sync(0xffffffffu, mi, off);
        if (ov > mv || (ov == mv && oi < mi)) { mv = ov; mi = oi; }
    }

    if (lane == 0) {
        float ms = 1.0f / (1.0f + expf(-mv));
        out[OFF_MS + wid] = ms;
        out[OFF_LB + wid] = (float)mi;

        const float* dl = deltas  + (size_t)wid * 4;
        const float* an = anchors + (size_t)n * 4;
        float a0 = an[0], a1 = an[1], a2 = an[2], a3 = an[3];
        float aw = a2 - a0, ah = a3 - a1;
        float acx = a0 + 0.5f * aw, acy = a1 + 0.5f * ah;
        float dx = dl[0], dy = dl[1];
        float dw = fminf(dl[2], 4.0f), dh = fminf(dl[3], 4.0f);
        float pcx = dx * aw + acx, pcy = dy * ah + acy;
        float pw = expf(dw) * aw, ph = expf(dh) * ah;
        float x1 = fminf(fmaxf(pcx - 0.5f * pw, 0.0f), 1.0f);
        float y1 = fminf(fmaxf(pcy - 0.5f * ph, 0.0f), 1.0f);
        float x2 = fminf(fmaxf(pcx + 0.5f * pw, 0.0f), 1.0f);
        float y2 = fminf(fmaxf(pcy + 0.5f * ph, 0.0f), 1.0f);

        float* bo = out + OFF_BOXES + (size_t)wid * 4;
        bo[0] = x1; bo[1] = y1; bo[2] = x2; bo[3] = y2;

        float w = x2 - x1, h = y2 - y1;
        u8 valid = (ms > 0.5f) && (w > 0.01f) && (h > 0.01f) &&
                   (w < 0.99f) && (h < 0.99f);
        g_validb[b][n] = valid;

        u32 ksb = ~__float_as_uint(ms);
        g_keys[b][n] = ((u64)ksb << 32) | (u32)n;

        int ix = min(15, max(0, (int)((x1 + x2) * 8.0f)));   /* cx*16 */
        int iy = min(15, max(0, (int)((y1 + y2) * 8.0f)));
        u8 cell = (u8)(ix * 16 + iy);
        g_cell[b][n] = cell;
        atomicAdd(&g_bins[b][cell], 1);
    }
}

/* ------------------------------------------------------------------ */
__global__ void prefix_kernel()
{
    int b = blockIdx.x;
    int t = threadIdx.x;   /* 256 */
    __shared__ int s[CELLS];
    int my = g_bins[b][t];
    s[t] = my;
    __syncthreads();
    for (int off = 1; off < CELLS; off <<= 1) {
        int v = (t >= off) ? s[t - off] : 0;
        __syncthreads();
        s[t] += v;
        __syncthreads();
    }
    g_off[b][t] = s[t] - my;   /* exclusive */
}

/* ------------------------------------------------------------------ */
__global__ void scatter_kernel(const float* __restrict__ out)
{
    int idx = blockIdx.x * blockDim.x + threadIdx.x;
    if (idx >= BB * NN) return;
    int b = idx / NN, n = idx % NN;

    u8 cell = g_cell[b][n];
    int pos = atomicAdd(&g_off[b][cell], 1);
    g_perm[b][pos] = (u16)n;
    float4 bx = *(const float4*)(out + OFF_BOXES + ((size_t)b * NN + n) * 4);
    g_sbox[b][pos]  = bx;
    g_sarea[b][pos] = (bx.z - bx.x) * (bx.w - bx.y);
    g_skey[b][pos]  = g_keys[b][n];
    g_sval[b][pos]  = g_validb[b][n];
}

/* ------------------------------------------------------------------ */
__global__ void taabb_kernel()
{
    int b = blockIdx.y, tile = blockIdx.x;
    int t = threadIdx.x;   /* 64 */
    float4 bx = g_sbox[b][tile * 64 + t];
    float mnx = bx.x, mny = bx.y, mxx = bx.z, mxy = bx.w;
    for (int off = 16; off; off >>= 1) {
        mnx = fminf(mnx, __shfl_xor_sync(0xffffffffu, mnx, off));
        mny = fminf(mny, __shfl_xor_sync(0xffffffffu, mny, off));
        mxx = fmaxf(mxx, __shfl_xor_sync(0xffffffffu, mxx, off));
        mxy = fmaxf(mxy, __shfl_xor_sync(0xffffffffu, mxy, off));
    }
    __shared__ float4 w0;
    if (t == 0) w0 = make_float4(mnx, mny, mxx, mxy);
    __syncthreads();
    if (t == 32) {
        g_taabb[b][tile] = make_float4(fminf(mnx, w0.x), fminf(mny, w0.y),
                                       fmaxf(mxx, w0.z), fmaxf(mxy, w0.w));
    }
}

/* ------------------------------------------------------------------ */
/* Kernel: sparse suppressor pairs over sorted boxes with AABB pruning */
__global__ void pairs_kernel()
{
    int b = blockIdx.y;
    int L = blockIdx.x;
    int cb = (int)((sqrtf(8.0f * (float)L + 1.0f) - 1.0f) * 0.5f);
    while ((cb + 1) * (cb + 2) / 2 <= L) cb++;
    while (cb * (cb + 1) / 2 > L) cb--;
    int rb = L - cb * (cb + 1) / 2;     /* rb <= cb */

    /* tile-level AABB overlap test (exact necessary condition) */
    float4 ra = g_taabb[b][rb];
    float4 ca = g_taabb[b][cb];
    if (!(fminf(ra.z, ca.z) > fmaxf(ra.x, ca.x) &&
          fminf(ra.w, ca.w) > fmaxf(ra.y, ca.y)))
        return;

    int t = threadIdx.x;  /* 64 */

    __shared__ float sx1[64], sy1[64], sx2[64], sy2[64], sar[64];
    __shared__ u64 skey[64];

    int cj = cb * 64 + t;
    float4 cbx = g_sbox[b][cj];
    sx1[t] = cbx.x; sy1[t] = cbx.y; sx2[t] = cbx.z; sy2[t] = cbx.w;
    sar[t] = g_sarea[b][cj];
    skey[t] = g_skey[b][cj];
    __syncthreads();

    int i = rb * 64 + t;
    float4 rbx = g_sbox[b][i];
    float ar = g_sarea[b][i];
    u64 kr = g_skey[b][i];

    /* row-level prune vs col tile AABB */
    bool active = (fminf(rbx.z, ca.z) > fmaxf(rbx.x, ca.x) &&
                   fminf(rbx.w, ca.w) > fmaxf(rbx.y, ca.y));
    if (!active) return;

    int jstart = (rb == cb) ? (t + 1) : 0;
    for (int j = jstart; j < 64; j++) {
        float ix1 = fmaxf(rbx.x, sx1[j]);
        float iy1 = fmaxf(rbx.y, sy1[j]);
        float ix2 = fminf(rbx.z, sx2[j]);
        float iy2 = fminf(rbx.w, sy2[j]);
        float inter = fmaxf(ix2 - ix1, 0.0f) * fmaxf(iy2 - iy1, 0.0f);
        float uni = ar + sar[j] - inter;
        if (inter > 0.5f * fmaxf(uni, 1e-9f)) {
            int ci = cb * 64 + j;
            int victim, supp;
            if (skey[j] < kr) { victim = i;  supp = ci; }
            else              { victim = ci; supp = i;  }
            int pos = atomicAdd(&g_cnt[b][victim], 1);
            if (pos < KCAP) g_list[b][victim][pos] = (u16)supp;
        }
    }
}

/* ------------------------------------------------------------------ */
/* NMS fixed point: one block per batch, keep[] in SMEM,               */
/* __syncthreads per sweep, exact convergence check.                   */
__global__ __launch_bounds__(1024, 1)
void nms_kernel(float* __restrict__ out)
{
    int b = blockIdx.x;
    int t = threadIdx.x;

    __shared__ u8 keep[NN];
    __shared__ int s_changed;

    u8  val[8];
    int cnt[8];
#pragma unroll
    for (int k = 0; k < 8; k++) {
        int i = t + k * 1024;
        val[k] = g_sval[b][i];
        keep[i] = val[k];
        cnt[k] = val[k] ? min(g_cnt[b][i], KCAP) : 0;
    }
    __syncthreads();

    for (int sw = 0; sw < 64; sw++) {
        if (t == 0) s_changed = 0;
        __syncthreads();

        bool ch = false;
#pragma unroll
        for (int k = 0; k < 8; k++) {
            int c = cnt[k];
            if (c == 0) continue;
            int i = t + k * 1024;
            const u16* lp = g_list[b][i];
            u32 s = 0;
            int q = 0;
            for (; q + 4 <= c; q += 4) {
                ushort4 v = *(const ushort4*)(lp + q);
                s |= (u32)keep[v.x] | keep[v.y] | keep[v.z] | keep[v.w];
            }
            for (; q < c; q++) s |= keep[lp[q]];
            u8 nk = (u8)(s == 0);        /* val[k]==1 here */
            if (nk != keep[i]) { keep[i] = nk; ch = true; }
        }

        if (ch) s_changed = 1;
        __syncthreads();
        if (s_changed == 0) break;
    }

    /* scatter keep back to original order */
#pragma unroll
    for (int k = 0; k < 8; k++) {
        int i = t + k * 1024;
        out[OFF_KEEP + b * NN + g_perm[b][i]] = (float)keep[i];
    }
}

/* ------------------------------------------------------------------ */
extern "C" void kernel_launch(void* const* d_in, const int* in_sizes, int n_in,
                              void* d_out, int out_size)
{
    (void)in_sizes; (void)n_in; (void)out_size;
    const float* logits  = (const float*)d_in[0];
    const float* deltas  = (const float*)d_in[1];
    const float* anchors = (const float*)d_in[2];
    float* out = (float*)d_out;

    init_kernel<<<(BB * NN + 255) / 256, 256>>>();
    prep_kernel<<<(BB * NN * 32 + 255) / 256, 256>>>(logits, deltas, anchors, out);
    prefix_kernel<<<BB, CELLS>>>();
    scatter_kernel<<<(BB * NN + 255) / 256, 256>>>(out);
    {
        dim3 g(NT, BB);
        taabb_kernel<<<g, 64>>>();
    }
    {
        dim3 g(NT * (NT + 1) / 2, BB);
        pairs_kernel<<<g, 64>>>();
    }
    nms_kernel<<<BB, 1024>>>(out);
}